// round 13
// baseline (speedup 1.0000x reference)
#include <cuda_runtime.h>
#include <cuda_fp16.h>
#include <cstdint>

// Problem shape (fixed): B=64, T=1000, I=512, O=256
#define SNN_B 64
#define SNN_T 1000
#define SNN_I 512
#define SNN_O 256
#define ALPHA 0.95f
#define BETA  0.9f

#define CHUNKS 8
#define CHUNK_L 125
#define CHAINS (SNN_B * SNN_O)   // 16384
#define MROWS (SNN_B * SNN_T)    // 64000
#define NTILES (SNN_B * CHUNKS)  // 512

__device__ __half  g_h[(size_t)MROWS * SNN_O];
__device__ float4  g_end[NTILES * 128];    // per (b,chunk): 128 x {f0,o0,f1,o1}
__device__ uint32_t g_flag[NTILES];

__device__ __forceinline__ uint32_t smem_u32(const void* p) {
    uint32_t a;
    asm("{ .reg .u64 t; cvta.to.shared.u64 t, %1; cvt.u32.u64 %0, t; }" : "=r"(a) : "l"(p));
    return a;
}
__device__ __forceinline__ uint32_t ld_acq(const uint32_t* p) {
    uint32_t v;
    asm volatile("ld.global.acquire.gpu.u32 %0, [%1];" : "=r"(v) : "l"(p));
    return v;
}
__device__ __forceinline__ void st_rel(uint32_t* p, uint32_t v) {
    asm volatile("st.global.release.gpu.u32 [%0], %1;" :: "l"(p), "r"(v));
}

// ===========================================================================
// Kernel 1: FP16 MMA GEMM (R5 config — measured fastest). 128x128 tile,
// BK=32 halves, 256 threads, 8 warps (4x2), single-buffer smem.
// Also clears the scan flags (stream order makes this replay-safe).
// ===========================================================================
#define GBM 128
#define GBN 128
#define BKH 32

__global__ __launch_bounds__(256, 1)
void snn_gemm_f16(const float* __restrict__ A,
                  const float* __restrict__ W,
                  __half* __restrict__ H)
{
    __shared__ __align__(16) __half Asm[GBM * BKH];   // 8 KB
    __shared__ __align__(16) __half Bsm[GBN * BKH];   // 8 KB

    const int tid  = threadIdx.x;
    const int lane = tid & 31;
    const int wid  = tid >> 5;
    const int wm   = wid & 3;
    const int wn   = wid >> 2;
    const int g    = lane >> 2;
    const int t4   = lane & 3;

    const int bn = blockIdx.x * GBN;     // x = N (2): adjacent CTAs share A rows
    const int bm = blockIdx.y * GBM;     // y = M (500)

    // clear scan flags for the kernel that follows in stream order
    if (blockIdx.x == 0 && tid == 0) {
        g_flag[blockIdx.y] = 0;
        if (blockIdx.y < NTILES - 500) g_flag[500 + blockIdx.y] = 0;
    }

    const int lrow = tid >> 1;
    const int lc0  = (tid & 1) * 16;
    const float* Ap = A + (size_t)(bm + lrow) * SNN_I + lc0;
    const float* Wp = W + (size_t)(bn + lrow) * SNN_I + lc0;

    const uint32_t sA = smem_u32(Asm);
    const uint32_t sB = smem_u32(Bsm);
    const int xrow = (lrow >> 1) & 3;

    float4 pa[4], pb[4];
    #pragma unroll
    for (int j = 0; j < 4; j++) {
        pa[j] = *(const float4*)(Ap + j * 4);
        pb[j] = *(const float4*)(Wp + j * 4);
    }

    float c[2][8][4];
    #pragma unroll
    for (int mt = 0; mt < 2; mt++)
        #pragma unroll
        for (int nt = 0; nt < 8; nt++)
            #pragma unroll
            for (int q = 0; q < 4; q++)
                c[mt][nt][q] = 0.0f;

    #pragma unroll 1
    for (int kt = 0; kt < SNN_I / BKH; kt++) {
        #pragma unroll
        for (int j = 0; j < 4; j++) {
            const int colb = (lc0 + j * 4) * 2;
            const int seg  = colb >> 4;
            const int rem  = colb & 15;
            const uint32_t off = lrow * 64 + (((seg ^ xrow) << 4) | rem);
            __half2 a0 = __floats2half2_rn(pa[j].x, pa[j].y);
            __half2 a1 = __floats2half2_rn(pa[j].z, pa[j].w);
            __half2 b0 = __floats2half2_rn(pb[j].x, pb[j].y);
            __half2 b1 = __floats2half2_rn(pb[j].z, pb[j].w);
            uint2 av = {*(uint32_t*)&a0, *(uint32_t*)&a1};
            uint2 bv = {*(uint32_t*)&b0, *(uint32_t*)&b1};
            *(uint2*)((char*)Asm + off) = av;
            *(uint2*)((char*)Bsm + off) = bv;
        }
        __syncthreads();

        if (kt + 1 < SNN_I / BKH) {
            const float* Apn = Ap + (kt + 1) * BKH;
            const float* Wpn = Wp + (kt + 1) * BKH;
            #pragma unroll
            for (int j = 0; j < 4; j++) {
                pa[j] = *(const float4*)(Apn + j * 4);
                pb[j] = *(const float4*)(Wpn + j * 4);
            }
        }

        #pragma unroll
        for (int s = 0; s < 2; s++) {
            uint32_t af[2][4];
            #pragma unroll
            for (int mt = 0; mt < 2; mt++) {
                const int row = wm * 32 + mt * 16 + (lane & 15);
                const int seg = s * 2 + (lane >> 4);
                const uint32_t addr = sA + row * 64 + ((seg ^ ((row >> 1) & 3)) << 4);
                asm volatile(
                    "ldmatrix.sync.aligned.m8n8.x4.shared.b16 {%0,%1,%2,%3}, [%4];"
                    : "=r"(af[mt][0]), "=r"(af[mt][1]), "=r"(af[mt][2]), "=r"(af[mt][3])
                    : "r"(addr));
            }
            uint32_t bf[4][4];
            #pragma unroll
            for (int p = 0; p < 4; p++) {
                const int row = wn * 64 + p * 16 + (lane & 15);
                const int seg = s * 2 + (lane >> 4);
                const uint32_t addr = sB + row * 64 + ((seg ^ ((row >> 1) & 3)) << 4);
                asm volatile(
                    "ldmatrix.sync.aligned.m8n8.x4.shared.b16 {%0,%1,%2,%3}, [%4];"
                    : "=r"(bf[p][0]), "=r"(bf[p][1]), "=r"(bf[p][2]), "=r"(bf[p][3])
                    : "r"(addr));
            }
            #pragma unroll
            for (int mt = 0; mt < 2; mt++)
                #pragma unroll
                for (int nt = 0; nt < 8; nt++) {
                    const int p = nt >> 1, hi = nt & 1;
                    asm volatile(
                        "mma.sync.aligned.m16n8k16.row.col.f32.f16.f16.f32 "
                        "{%0,%1,%2,%3}, {%4,%5,%6,%7}, {%8,%9}, {%0,%1,%2,%3};"
                        : "+f"(c[mt][nt][0]), "+f"(c[mt][nt][1]),
                          "+f"(c[mt][nt][2]), "+f"(c[mt][nt][3])
                        : "r"(af[mt][0]), "r"(af[mt][1]), "r"(af[mt][2]), "r"(af[mt][3]),
                          "r"(bf[p][hi]), "r"(bf[p][hi + 2]));
                }
        }
        __syncthreads();
    }

    #pragma unroll
    for (int mt = 0; mt < 2; mt++) {
        #pragma unroll
        for (int nt = 0; nt < 8; nt++) {
            const int row = bm + wm * 32 + mt * 16 + g;
            const int col = bn + wn * 64 + nt * 8 + t4 * 2;
            __half2 v0 = __floats2half2_rn(c[mt][nt][0], c[mt][nt][1]);
            __half2 v1 = __floats2half2_rn(c[mt][nt][2], c[mt][nt][3]);
            *(__half2*)(H + (size_t)row * SNN_O + col)       = v0;
            *(__half2*)(H + (size_t)(row + 8) * SNN_O + col) = v1;
        }
    }
}

// ===========================================================================
// Kernel 2: single-pass decoupled-lookback scan.
//   512 CTAs (one per (b,chunk)) x 128 threads x 2 chains — ALL resident in
//   one wave (regs~40, smem~0), so spin-waits cannot deadlock.
//   Pass A: local scan from zero (H chunk is L2-hot), publish ends + flag.
//   Lookback: wait for <=7 predecessor flags, combine with closed-form M^125.
//   Pass B: rescan from exact prefix (L1/L2 hits) and write output.
// ===========================================================================
__global__ __launch_bounds__(128)
void snn_scan_lookback(const __half* __restrict__ H, float* __restrict__ out)
{
    const int tid  = threadIdx.x;          // o2 = tid
    const int cidx = blockIdx.x & 7;
    const int b    = blockIdx.x >> 3;

    const size_t ebase = ((size_t)b * SNN_T + cidx * CHUNK_L) * SNN_O + tid * 2;
    const __half2* hp = (const __half2*)(H + ebase);

    // ---- Pass A: local scan from zero ----
    float f0 = 0.f, o0 = 0.f, f1 = 0.f, o1 = 0.f;
    #pragma unroll 1
    for (int t = 0; t < CHUNK_L; t += 5) {
        __half2 v[5];
        #pragma unroll
        for (int j = 0; j < 5; j++)
            v[j] = hp[(size_t)(t + j) * (SNN_O / 2)];
        #pragma unroll
        for (int j = 0; j < 5; j++) {
            float h0 = __low2float(v[j]), h1 = __high2float(v[j]);
            float n0 = fmaf(ALPHA, f0, h0);
            float n1 = fmaf(ALPHA, f1, h1);
            o0 = fmaf(BETA, o0, f0);
            o1 = fmaf(BETA, o1, f1);
            f0 = n0; f1 = n1;
        }
    }

    // ---- Publish chunk-end states, then release flag ----
    g_end[(blockIdx.x << 7) | tid] = make_float4(f0, o0, f1, o1);
    __syncthreads();
    if (tid == 0) {
        __threadfence();
        st_rel(&g_flag[blockIdx.x], 1u);
    }

    // ---- Lookback: combine predecessor chunk ends ----
    float pf0 = 0.f, po0 = 0.f, pf1 = 0.f, po1 = 0.f;
    if (cidx > 0) {
        if (tid < cidx) {
            const uint32_t* fp = &g_flag[(b << 3) | tid];
            while (ld_acq(fp) == 0) { }
        }
        __syncthreads();

        const float aL = exp2f((float)CHUNK_L * log2f(ALPHA));
        const float bL = exp2f((float)CHUNK_L * log2f(BETA));
        const float cL = (aL - bL) / (ALPHA - BETA);
        for (int c2 = 0; c2 < cidx; c2++) {
            const float4 e = g_end[((((b << 3) | c2)) << 7) | tid];
            float nf0 = fmaf(aL, pf0, e.x);
            float no0 = fmaf(bL, po0, fmaf(cL, pf0, e.y));
            float nf1 = fmaf(aL, pf1, e.z);
            float no1 = fmaf(bL, po1, fmaf(cL, pf1, e.w));
            pf0 = nf0; po0 = no0; pf1 = nf1; po1 = no1;
        }
    }

    // ---- Pass B: rescan from exact init, write output ----
    float* op = out + ebase;
    f0 = pf0; o0 = po0; f1 = pf1; o1 = po1;
    #pragma unroll 1
    for (int t = 0; t < CHUNK_L; t += 5) {
        __half2 v[5];
        #pragma unroll
        for (int j = 0; j < 5; j++)
            v[j] = hp[(size_t)(t + j) * (SNN_O / 2)];
        #pragma unroll
        for (int j = 0; j < 5; j++) {
            float h0 = __low2float(v[j]), h1 = __high2float(v[j]);
            float n0 = fmaf(ALPHA, f0, h0);
            float n1 = fmaf(ALPHA, f1, h1);
            o0 = fmaf(BETA, o0, f0);
            o1 = fmaf(BETA, o1, f1);
            f0 = n0; f1 = n1;
            float2 w = {o0, o1};
            *(float2*)(op + (size_t)(t + j) * SNN_O) = w;
        }
    }
}

// ---------------------------------------------------------------------------
extern "C" void kernel_launch(void* const* d_in, const int* in_sizes, int n_in,
                              void* d_out, int out_size)
{
    const float* inputs = (const float*)d_in[0];   // (B, T, I)
    const float* W      = (const float*)d_in[1];   // (O, I)
    float* out = (float*)d_out;                    // (B, T, O) fp32

    __half* h;
    cudaGetSymbolAddress((void**)&h, g_h);

    dim3 gemm_grid(SNN_O / GBN, MROWS / GBM);      // (2, 500)
    snn_gemm_f16<<<gemm_grid, 256>>>(inputs, W, h);

    snn_scan_lookback<<<NTILES, 128>>>(h, out);    // 512 CTAs, one wave
}

// round 14
// speedup vs baseline: 1.1508x; 1.1508x over previous
#include <cuda_runtime.h>
#include <cuda_fp16.h>
#include <cstdint>

// Problem shape (fixed): B=64, T=1000, I=512, O=256
#define SNN_B 64
#define SNN_T 1000
#define SNN_I 512
#define SNN_O 256
#define ALPHA 0.95f
#define BETA  0.9f

#define CHUNKS 8
#define CHUNK_L 125
#define MROWS (SNN_B * SNN_T)    // 64000
#define NTILES (SNN_B * CHUNKS)  // 512

__device__ __half   g_h[(size_t)MROWS * SNN_O];
__device__ float2   g_end[NTILES * SNN_O];   // per (b,chunk): 256 x {f,o}
__device__ uint32_t g_flag[NTILES];

__device__ __forceinline__ uint32_t smem_u32(const void* p) {
    uint32_t a;
    asm("{ .reg .u64 t; cvta.to.shared.u64 t, %1; cvt.u32.u64 %0, t; }" : "=r"(a) : "l"(p));
    return a;
}
__device__ __forceinline__ uint32_t ld_acq(const uint32_t* p) {
    uint32_t v;
    asm volatile("ld.global.acquire.gpu.u32 %0, [%1];" : "=r"(v) : "l"(p));
    return v;
}
__device__ __forceinline__ void st_rel(uint32_t* p, uint32_t v) {
    asm volatile("st.global.release.gpu.u32 [%0], %1;" :: "l"(p), "r"(v));
}

// ===========================================================================
// Kernel 1: FP16 MMA GEMM (measured-best config). 128x128 tile, BK=32 halves,
// 256 threads, 8 warps (4x2), single-buffer smem. Clears scan flags.
// ===========================================================================
#define GBM 128
#define GBN 128
#define BKH 32

__global__ __launch_bounds__(256, 1)
void snn_gemm_f16(const float* __restrict__ A,
                  const float* __restrict__ W,
                  __half* __restrict__ H)
{
    __shared__ __align__(16) __half Asm[GBM * BKH];   // 8 KB
    __shared__ __align__(16) __half Bsm[GBN * BKH];   // 8 KB

    const int tid  = threadIdx.x;
    const int lane = tid & 31;
    const int wid  = tid >> 5;
    const int wm   = wid & 3;
    const int wn   = wid >> 2;
    const int g    = lane >> 2;
    const int t4   = lane & 3;

    const int bn = blockIdx.x * GBN;     // x = N (2)
    const int bm = blockIdx.y * GBM;     // y = M (500)

    // clear scan flags (stream order protects the consumer kernel)
    if (blockIdx.x == 0 && tid == 0) {
        g_flag[blockIdx.y] = 0;
        if (blockIdx.y < NTILES - 500) g_flag[500 + blockIdx.y] = 0;
    }

    const int lrow = tid >> 1;
    const int lc0  = (tid & 1) * 16;
    const float* Ap = A + (size_t)(bm + lrow) * SNN_I + lc0;
    const float* Wp = W + (size_t)(bn + lrow) * SNN_I + lc0;

    const uint32_t sA = smem_u32(Asm);
    const uint32_t sB = smem_u32(Bsm);
    const int xrow = (lrow >> 1) & 3;

    float4 pa[4], pb[4];
    #pragma unroll
    for (int j = 0; j < 4; j++) {
        pa[j] = *(const float4*)(Ap + j * 4);
        pb[j] = *(const float4*)(Wp + j * 4);
    }

    float c[2][8][4];
    #pragma unroll
    for (int mt = 0; mt < 2; mt++)
        #pragma unroll
        for (int nt = 0; nt < 8; nt++)
            #pragma unroll
            for (int q = 0; q < 4; q++)
                c[mt][nt][q] = 0.0f;

    #pragma unroll 1
    for (int kt = 0; kt < SNN_I / BKH; kt++) {
        #pragma unroll
        for (int j = 0; j < 4; j++) {
            const int colb = (lc0 + j * 4) * 2;
            const int seg  = colb >> 4;
            const int rem  = colb & 15;
            const uint32_t off = lrow * 64 + (((seg ^ xrow) << 4) | rem);
            __half2 a0 = __floats2half2_rn(pa[j].x, pa[j].y);
            __half2 a1 = __floats2half2_rn(pa[j].z, pa[j].w);
            __half2 b0 = __floats2half2_rn(pb[j].x, pb[j].y);
            __half2 b1 = __floats2half2_rn(pb[j].z, pb[j].w);
            uint2 av = {*(uint32_t*)&a0, *(uint32_t*)&a1};
            uint2 bv = {*(uint32_t*)&b0, *(uint32_t*)&b1};
            *(uint2*)((char*)Asm + off) = av;
            *(uint2*)((char*)Bsm + off) = bv;
        }
        __syncthreads();

        if (kt + 1 < SNN_I / BKH) {
            const float* Apn = Ap + (kt + 1) * BKH;
            const float* Wpn = Wp + (kt + 1) * BKH;
            #pragma unroll
            for (int j = 0; j < 4; j++) {
                pa[j] = *(const float4*)(Apn + j * 4);
                pb[j] = *(const float4*)(Wpn + j * 4);
            }
        }

        #pragma unroll
        for (int s = 0; s < 2; s++) {
            uint32_t af[2][4];
            #pragma unroll
            for (int mt = 0; mt < 2; mt++) {
                const int row = wm * 32 + mt * 16 + (lane & 15);
                const int seg = s * 2 + (lane >> 4);
                const uint32_t addr = sA + row * 64 + ((seg ^ ((row >> 1) & 3)) << 4);
                asm volatile(
                    "ldmatrix.sync.aligned.m8n8.x4.shared.b16 {%0,%1,%2,%3}, [%4];"
                    : "=r"(af[mt][0]), "=r"(af[mt][1]), "=r"(af[mt][2]), "=r"(af[mt][3])
                    : "r"(addr));
            }
            uint32_t bf[4][4];
            #pragma unroll
            for (int p = 0; p < 4; p++) {
                const int row = wn * 64 + p * 16 + (lane & 15);
                const int seg = s * 2 + (lane >> 4);
                const uint32_t addr = sB + row * 64 + ((seg ^ ((row >> 1) & 3)) << 4);
                asm volatile(
                    "ldmatrix.sync.aligned.m8n8.x4.shared.b16 {%0,%1,%2,%3}, [%4];"
                    : "=r"(bf[p][0]), "=r"(bf[p][1]), "=r"(bf[p][2]), "=r"(bf[p][3])
                    : "r"(addr));
            }
            #pragma unroll
            for (int mt = 0; mt < 2; mt++)
                #pragma unroll
                for (int nt = 0; nt < 8; nt++) {
                    const int p = nt >> 1, hi = nt & 1;
                    asm volatile(
                        "mma.sync.aligned.m16n8k16.row.col.f32.f16.f16.f32 "
                        "{%0,%1,%2,%3}, {%4,%5,%6,%7}, {%8,%9}, {%0,%1,%2,%3};"
                        : "+f"(c[mt][nt][0]), "+f"(c[mt][nt][1]),
                          "+f"(c[mt][nt][2]), "+f"(c[mt][nt][3])
                        : "r"(af[mt][0]), "r"(af[mt][1]), "r"(af[mt][2]), "r"(af[mt][3]),
                          "r"(bf[p][hi]), "r"(bf[p][hi + 2]));
                }
        }
        __syncthreads();
    }

    #pragma unroll
    for (int mt = 0; mt < 2; mt++) {
        #pragma unroll
        for (int nt = 0; nt < 8; nt++) {
            const int row = bm + wm * 32 + mt * 16 + g;
            const int col = bn + wn * 64 + nt * 8 + t4 * 2;
            __half2 v0 = __floats2half2_rn(c[mt][nt][0], c[mt][nt][1]);
            __half2 v1 = __floats2half2_rn(c[mt][nt][2], c[mt][nt][3]);
            *(__half2*)(H + (size_t)row * SNN_O + col)       = v0;
            *(__half2*)(H + (size_t)(row + 8) * SNN_O + col) = v1;
        }
    }
}

// ===========================================================================
// Kernel 2: smem-staged lookback scan. One CTA per (b, chunk), 256 threads.
//   bid = cidx*64 + b  -> chunk index varies SLOWEST: every predecessor has a
//   strictly lower bid, so in-dispatch-order scheduling cannot deadlock the
//   spin even across waves (512 CTAs, 3/SM at 62.5KB smem -> ~1.2 waves).
//   Stage: chunk of H is CONTIGUOUS (62.5 KB) -> bulk uint4 copy (deep MLP),
//   then both scan passes read smem (LDS), not gmem.
// ===========================================================================
#define CHUNK_BYTES (CHUNK_L * SNN_O * 2)   // 64000

__global__ __launch_bounds__(256)
void snn_scan_smem(const __half* __restrict__ H, float* __restrict__ out)
{
    extern __shared__ __align__(16) char smem[];
    __half* S = (__half*)smem;

    const int tid  = threadIdx.x;            // chain o = tid
    const int cidx = blockIdx.x >> 6;        // chunk (slowest)
    const int b    = blockIdx.x & 63;

    const size_t gbase = ((size_t)b * SNN_T + cidx * CHUNK_L) * SNN_O;

    // ---- bulk copy chunk into smem: 4000 uint4, coalesced, deep MLP ----
    {
        const uint4* src = (const uint4*)(H + gbase);
        uint4* dst = (uint4*)smem;
        #pragma unroll
        for (int i = 0; i < CHUNK_BYTES / 16 / 256; i++)
            dst[i * 256 + tid] = src[i * 256 + tid];
        // remainder: 4000 - 15*256 = 160
        const int r = 15 * 256 + tid;
        if (tid < 160) dst[r] = src[r];
    }
    __syncthreads();

    // ---- Pass A: local scan from zero (smem reads) ----
    float f = 0.0f, o = 0.0f;
    {
        const __half* cp = S + tid;
        #pragma unroll 1
        for (int t = 0; t < CHUNK_L; t += 5) {
            float v[5];
            #pragma unroll
            for (int j = 0; j < 5; j++)
                v[j] = __half2float(cp[(t + j) * SNN_O]);
            #pragma unroll
            for (int j = 0; j < 5; j++) {
                float nf = fmaf(ALPHA, f, v[j]);
                o = fmaf(BETA, o, f);
                f = nf;
            }
        }
    }

    // ---- Publish end state + flag ----
    g_end[((b * CHUNKS + cidx) << 8) | tid] = make_float2(f, o);
    __syncthreads();
    if (tid == 0) {
        __threadfence();
        st_rel(&g_flag[(b << 3) | cidx], 1u);
    }

    float* op = out + gbase + tid;

    if (cidx == 0) {
        // chunk 0: local scan IS the true scan — single pass, write out now
        float ff = 0.0f, oo = 0.0f;
        const __half* cp = S + tid;
        #pragma unroll 1
        for (int t = 0; t < CHUNK_L; t += 5) {
            float v[5];
            #pragma unroll
            for (int j = 0; j < 5; j++)
                v[j] = __half2float(cp[(t + j) * SNN_O]);
            #pragma unroll
            for (int j = 0; j < 5; j++) {
                float nf = fmaf(ALPHA, ff, v[j]);
                oo = fmaf(BETA, oo, ff);
                ff = nf;
                op[(t + j) * SNN_O] = oo;
            }
        }
        return;
    }

    // ---- Lookback: wait for predecessors, combine with closed-form M^125 ----
    if (tid < cidx) {
        const uint32_t* fp = &g_flag[(b << 3) | tid];
        while (ld_acq(fp) == 0) { }
    }
    __syncthreads();

    const float aL = exp2f((float)CHUNK_L * log2f(ALPHA));
    const float bL = exp2f((float)CHUNK_L * log2f(BETA));
    const float cL = (aL - bL) / (ALPHA - BETA);

    float pf = 0.f, po = 0.f;
    for (int c2 = 0; c2 < cidx; c2++) {
        const float2 e = g_end[((b * CHUNKS + c2) << 8) | tid];
        float nf = fmaf(aL, pf, e.x);
        float no = fmaf(bL, po, fmaf(cL, pf, e.y));
        pf = nf; po = no;
    }

    // ---- Pass B: rescan from exact prefix (smem reads), write out ----
    f = pf; o = po;
    {
        const __half* cp = S + tid;
        #pragma unroll 1
        for (int t = 0; t < CHUNK_L; t += 5) {
            float v[5];
            #pragma unroll
            for (int j = 0; j < 5; j++)
                v[j] = __half2float(cp[(t + j) * SNN_O]);
            #pragma unroll
            for (int j = 0; j < 5; j++) {
                float nf = fmaf(ALPHA, f, v[j]);
                o = fmaf(BETA, o, f);
                f = nf;
                op[(t + j) * SNN_O] = o;
            }
        }
    }
}

// ---------------------------------------------------------------------------
extern "C" void kernel_launch(void* const* d_in, const int* in_sizes, int n_in,
                              void* d_out, int out_size)
{
    const float* inputs = (const float*)d_in[0];   // (B, T, I)
    const float* W      = (const float*)d_in[1];   // (O, I)
    float* out = (float*)d_out;                    // (B, T, O) fp32

    __half* h;
    cudaGetSymbolAddress((void**)&h, g_h);

    dim3 gemm_grid(SNN_O / GBN, MROWS / GBM);      // (2, 500)
    snn_gemm_f16<<<gemm_grid, 256>>>(inputs, W, h);

    cudaFuncSetAttribute(snn_scan_smem, cudaFuncAttributeMaxDynamicSharedMemorySize, CHUNK_BYTES);
    snn_scan_smem<<<NTILES, 256, CHUNK_BYTES>>>(h, out);
}

// round 16
// speedup vs baseline: 1.3664x; 1.1873x over previous
#include <cuda_runtime.h>
#include <cuda_fp16.h>
#include <cstdint>

// Problem shape (fixed): B=64, T=1000, I=512, O=256
#define SNN_B 64
#define SNN_T 1000
#define SNN_I 512
#define SNN_O 256
#define ALPHA 0.95f
#define BETA  0.9f

#define CHUNKS 8
#define CHUNK_L 125
#define MROWS (SNN_B * SNN_T)    // 64000
#define NTILES (SNN_B * CHUNKS)  // 512

__device__ __half   g_h[(size_t)MROWS * SNN_O];
__device__ float2   g_end[NTILES * SNN_O];
__device__ uint32_t g_flag[NTILES];

__device__ __forceinline__ uint32_t smem_u32(const void* p) {
    uint32_t a;
    asm("{ .reg .u64 t; cvta.to.shared.u64 t, %1; cvt.u32.u64 %0, t; }" : "=r"(a) : "l"(p));
    return a;
}
__device__ __forceinline__ uint32_t ld_acq(const uint32_t* p) {
    uint32_t v;
    asm volatile("ld.global.acquire.gpu.u32 %0, [%1];" : "=r"(v) : "l"(p));
    return v;
}
__device__ __forceinline__ void st_rel(uint32_t* p, uint32_t v) {
    asm volatile("st.global.release.gpu.u32 [%0], %1;" :: "l"(p), "r"(v));
}

// ===========================================================================
// Kernel 1: FP16 MMA GEMM, CTA tile M=64 x N=256 (FULL N -> A read ONCE).
//   1000 CTAs, 256 threads, 8 warps (2 M-bands x 4 N-bands), warp tile 32x64.
//   BK=32 halves (64B smem rows, seg^=(row>>1)&3 swizzle). Single-buffer.
// ===========================================================================
#define GBM 64
#define BKH 32

__global__ __launch_bounds__(256, 1)
void snn_gemm_f16(const float* __restrict__ A,
                  const float* __restrict__ W,
                  __half* __restrict__ H)
{
    __shared__ __align__(16) __half Asm[GBM * BKH];     // 4 KB
    __shared__ __align__(16) __half Bsm[SNN_O * BKH];   // 16 KB

    const int tid  = threadIdx.x;
    const int lane = tid & 31;
    const int wid  = tid >> 5;
    const int wm   = wid & 1;        // M band (2 x 32 rows)
    const int wn   = wid >> 1;       // N band (4 x 64 cols)
    const int g    = lane >> 2;
    const int t4   = lane & 3;

    const int bm = blockIdx.x * GBM;   // 1000 tiles

    // clear scan flags (stream order protects the consumer kernel)
    if (tid == 0 && blockIdx.x < NTILES) g_flag[blockIdx.x] = 0;

    // Loaders (per K-tile): A = 512 float4 (2/thread), B = 2048 float4 (8/thread)
    // mapping: idx -> row = idx>>3, 4-float group j = idx&7
    const uint32_t sA = smem_u32(Asm);
    const uint32_t sB = smem_u32(Bsm);

    const int arow0 = (tid >> 3);            // A rows: tid>>3 + 32*i  (i=0,1)
    const int aj    = tid & 7;               // 4-float group within row
    const float* Ap = A + (size_t)(bm + arow0) * SNN_I + aj * 4;
    const float* Wp = W + (size_t)arow0 * SNN_I + aj * 4;

    float4 pa[2], pb[8];
    #pragma unroll
    for (int i = 0; i < 2; i++)
        pa[i] = *(const float4*)(Ap + (size_t)(32 * i) * SNN_I);
    #pragma unroll
    for (int i = 0; i < 8; i++)
        pb[i] = *(const float4*)(Wp + (size_t)(32 * i) * SNN_I);

    float c[2][8][4];
    #pragma unroll
    for (int mt = 0; mt < 2; mt++)
        #pragma unroll
        for (int nt = 0; nt < 8; nt++)
            #pragma unroll
            for (int q = 0; q < 4; q++)
                c[mt][nt][q] = 0.0f;

    #pragma unroll 1
    for (int kt = 0; kt < SNN_I / BKH; kt++) {
        // store prefetched tile (swizzled): group j -> byte col j*8
        {
            const int colb = aj * 8;
            const int seg  = colb >> 4;        // j>>1
            const int rem  = colb & 15;        // (j&1)*8
            #pragma unroll
            for (int i = 0; i < 2; i++) {
                const int row = arow0 + 32 * i;
                const uint32_t off = row * 64 + (((seg ^ ((row >> 1) & 3)) << 4) | rem);
                __half2 a0 = __floats2half2_rn(pa[i].x, pa[i].y);
                __half2 a1 = __floats2half2_rn(pa[i].z, pa[i].w);
                uint2 av = {*(uint32_t*)&a0, *(uint32_t*)&a1};
                *(uint2*)((char*)Asm + off) = av;
            }
            #pragma unroll
            for (int i = 0; i < 8; i++) {
                const int row = arow0 + 32 * i;
                const uint32_t off = row * 64 + (((seg ^ ((row >> 1) & 3)) << 4) | rem);
                __half2 b0 = __floats2half2_rn(pb[i].x, pb[i].y);
                __half2 b1 = __floats2half2_rn(pb[i].z, pb[i].w);
                uint2 bv = {*(uint32_t*)&b0, *(uint32_t*)&b1};
                *(uint2*)((char*)Bsm + off) = bv;
            }
        }
        __syncthreads();

        if (kt + 1 < SNN_I / BKH) {
            const int koff = (kt + 1) * BKH;
            #pragma unroll
            for (int i = 0; i < 2; i++)
                pa[i] = *(const float4*)(Ap + (size_t)(32 * i) * SNN_I + koff);
            #pragma unroll
            for (int i = 0; i < 8; i++)
                pb[i] = *(const float4*)(Wp + (size_t)(32 * i) * SNN_I + koff);
        }

        #pragma unroll
        for (int s = 0; s < 2; s++) {
            uint32_t af[2][4];
            #pragma unroll
            for (int mt = 0; mt < 2; mt++) {
                const int row = wm * 32 + mt * 16 + (lane & 15);
                const int seg = s * 2 + (lane >> 4);
                const uint32_t addr = sA + row * 64 + ((seg ^ ((row >> 1) & 3)) << 4);
                asm volatile(
                    "ldmatrix.sync.aligned.m8n8.x4.shared.b16 {%0,%1,%2,%3}, [%4];"
                    : "=r"(af[mt][0]), "=r"(af[mt][1]), "=r"(af[mt][2]), "=r"(af[mt][3])
                    : "r"(addr));
            }
            uint32_t bf[4][4];
            #pragma unroll
            for (int p = 0; p < 4; p++) {
                const int row = wn * 64 + p * 16 + (lane & 15);
                const int seg = s * 2 + (lane >> 4);
                const uint32_t addr = sB + row * 64 + ((seg ^ ((row >> 1) & 3)) << 4);
                asm volatile(
                    "ldmatrix.sync.aligned.m8n8.x4.shared.b16 {%0,%1,%2,%3}, [%4];"
                    : "=r"(bf[p][0]), "=r"(bf[p][1]), "=r"(bf[p][2]), "=r"(bf[p][3])
                    : "r"(addr));
            }
            #pragma unroll
            for (int mt = 0; mt < 2; mt++)
                #pragma unroll
                for (int nt = 0; nt < 8; nt++) {
                    const int p = nt >> 1, hi = nt & 1;
                    asm volatile(
                        "mma.sync.aligned.m16n8k16.row.col.f32.f16.f16.f32 "
                        "{%0,%1,%2,%3}, {%4,%5,%6,%7}, {%8,%9}, {%0,%1,%2,%3};"
                        : "+f"(c[mt][nt][0]), "+f"(c[mt][nt][1]),
                          "+f"(c[mt][nt][2]), "+f"(c[mt][nt][3])
                        : "r"(af[mt][0]), "r"(af[mt][1]), "r"(af[mt][2]), "r"(af[mt][3]),
                          "r"(bf[p][hi]), "r"(bf[p][hi + 2]));
                }
        }
        __syncthreads();
    }

    #pragma unroll
    for (int mt = 0; mt < 2; mt++) {
        #pragma unroll
        for (int nt = 0; nt < 8; nt++) {
            const int row = bm + wm * 32 + mt * 16 + g;
            const int col = wn * 64 + nt * 8 + t4 * 2;
            __half2 v0 = __floats2half2_rn(c[mt][nt][0], c[mt][nt][1]);
            __half2 v1 = __floats2half2_rn(c[mt][nt][2], c[mt][nt][3]);
            *(__half2*)(H + (size_t)row * SNN_O + col)       = v0;
            *(__half2*)(H + (size_t)(row + 8) * SNN_O + col) = v1;
        }
    }
}

// ===========================================================================
// Kernel 2: smem-staged lookback scan (R9 config — measured 21.2us).
// ===========================================================================
#define CHUNK_BYTES (CHUNK_L * SNN_O * 2)   // 64000

__global__ __launch_bounds__(256)
void snn_scan_smem(const __half* __restrict__ H, float* __restrict__ out)
{
    extern __shared__ __align__(16) char smem[];
    __half* S = (__half*)smem;

    const int tid  = threadIdx.x;            // chain o = tid
    const int cidx = blockIdx.x >> 6;        // chunk (slowest -> deadlock-free)
    const int b    = blockIdx.x & 63;

    const size_t gbase = ((size_t)b * SNN_T + cidx * CHUNK_L) * SNN_O;

    // bulk copy chunk into smem: 4000 uint4, coalesced, deep MLP
    {
        const uint4* src = (const uint4*)(H + gbase);
        uint4* dst = (uint4*)smem;
        #pragma unroll
        for (int i = 0; i < CHUNK_BYTES / 16 / 256; i++)
            dst[i * 256 + tid] = src[i * 256 + tid];
        const int r = 15 * 256 + tid;
        if (tid < 160) dst[r] = src[r];
    }
    __syncthreads();

    // Pass A: local scan from zero (smem reads)
    float f = 0.0f, o = 0.0f;
    {
        const __half* cp = S + tid;
        #pragma unroll 1
        for (int t = 0; t < CHUNK_L; t += 5) {
            float v[5];
            #pragma unroll
            for (int j = 0; j < 5; j++)
                v[j] = __half2float(cp[(t + j) * SNN_O]);
            #pragma unroll
            for (int j = 0; j < 5; j++) {
                float nf = fmaf(ALPHA, f, v[j]);
                o = fmaf(BETA, o, f);
                f = nf;
            }
        }
    }

    g_end[((b * CHUNKS + cidx) << 8) | tid] = make_float2(f, o);
    __syncthreads();
    if (tid == 0) {
        __threadfence();
        st_rel(&g_flag[(b << 3) | cidx], 1u);
    }

    float* op = out + gbase + tid;

    if (cidx == 0) {
        float ff = 0.0f, oo = 0.0f;
        const __half* cp = S + tid;
        #pragma unroll 1
        for (int t = 0; t < CHUNK_L; t += 5) {
            float v[5];
            #pragma unroll
            for (int j = 0; j < 5; j++)
                v[j] = __half2float(cp[(t + j) * SNN_O]);
            #pragma unroll
            for (int j = 0; j < 5; j++) {
                float nf = fmaf(ALPHA, ff, v[j]);
                oo = fmaf(BETA, oo, ff);
                ff = nf;
                op[(t + j) * SNN_O] = oo;
            }
        }
        return;
    }

    if (tid < cidx) {
        const uint32_t* fp = &g_flag[(b << 3) | tid];
        while (ld_acq(fp) == 0) { }
    }
    __syncthreads();

    const float aL = exp2f((float)CHUNK_L * log2f(ALPHA));
    const float bL = exp2f((float)CHUNK_L * log2f(BETA));
    const float cL = (aL - bL) / (ALPHA - BETA);

    float pf = 0.f, po = 0.f;
    for (int c2 = 0; c2 < cidx; c2++) {
        const float2 e = g_end[((b * CHUNKS + c2) << 8) | tid];
        float nf = fmaf(aL, pf, e.x);
        float no = fmaf(bL, po, fmaf(cL, pf, e.y));
        pf = nf; po = no;
    }

    f = pf; o = po;
    {
        const __half* cp = S + tid;
        #pragma unroll 1
        for (int t = 0; t < CHUNK_L; t += 5) {
            float v[5];
            #pragma unroll
            for (int j = 0; j < 5; j++)
                v[j] = __half2float(cp[(t + j) * SNN_O]);
            #pragma unroll
            for (int j = 0; j < 5; j++) {
                float nf = fmaf(ALPHA, f, v[j]);
                o = fmaf(BETA, o, f);
                f = nf;
                op[(t + j) * SNN_O] = o;
            }
        }
    }
}

// ---------------------------------------------------------------------------
extern "C" void kernel_launch(void* const* d_in, const int* in_sizes, int n_in,
                              void* d_out, int out_size)
{
    const float* inputs = (const float*)d_in[0];   // (B, T, I)
    const float* W      = (const float*)d_in[1];   // (O, I)
    float* out = (float*)d_out;                    // (B, T, O) fp32

    __half* h;
    cudaGetSymbolAddress((void**)&h, g_h);

    snn_gemm_f16<<<MROWS / GBM, 256>>>(inputs, W, h);   // 1000 CTAs, A read once

    cudaFuncSetAttribute(snn_scan_smem, cudaFuncAttributeMaxDynamicSharedMemorySize, CHUNK_BYTES);
    snn_scan_smem<<<NTILES, 256, CHUNK_BYTES>>>(h, out);
}